// round 16
// baseline (speedup 1.0000x reference)
#include <cuda_runtime.h>
#include <cuda_fp16.h>
#include <cstdint>
#include <cstring>

// ---------------------------------------------------------------------------
// SyntaxGCN: GCNConv(512->256) + relu + global_mean_pool + linear(256->1) + sigmoid
// R15: fp8 (e4m3) single-pass GEMM via mma.sync.m16n8k32 — 256 MMAs/warp vs
//      512 for fp16 (the measured issue ceiling). x scaled by dinv*16, W by 64,
//      epilogue /1024; hs stays fp16. Error budget calibrated by R12's measured
//      washout (3 x 5e-4 sources -> 3.9e-6): fp8's ~2.5% element error -> ~2e-4
//      final, 5x under the 1e-3 tolerance.
// ---------------------------------------------------------------------------

constexpr int N_NODES  = 20000;
constexpr int N_EDGES  = 320000;
constexpr int IN_DIM   = 512;
constexpr int HID      = 256;
constexpr int N_GRAPHS = 256;
constexpr int CSR_CAP  = 128;

constexpr float SX = 16.f;                 // x*dinv scale into fp8
constexpr float SW = 64.f;                 // W scale into fp8
constexpr float RSCALE = 1.f / (16.f * 64.f);

constexpr int TILE_M = 128;
constexpr int TILE_N = 128;
constexpr int TKB    = 64;                 // fp8 k-bytes per chunk
constexpr int NCHUNK = IN_DIM / TKB;       // 8
constexpr int RSTRB  = 80;                 // smem row stride BYTES (16B-aligned, LDSM conflict-free)
constexpr int MATB   = TILE_M * RSTRB;     // 10240 bytes per tile
constexpr int OFF_B  = MATB;
constexpr int STAGEB = 2 * MATB;           // 20480
constexpr int SMEM_BYTES = 2 * STAGEB;     // 40960

// Scratch (device globals)
__device__ uint2  g_hsh[N_NODES * HID / 4];       // hs fp16 (half2 pairs)
__device__ float  g_dinv[N_NODES];
__device__ int    g_cnt[N_NODES];
__device__ int    g_csr[N_NODES * CSR_CAP];
__device__ float4 g_pooled[N_GRAPHS * HID / 4];
__device__ float  g_counts[N_GRAPHS];
__device__ uint4  g_x8[N_NODES * IN_DIM / 16];    // fp8 x*dinv*SX, [m][k]
__device__ uint4  g_w8[HID * IN_DIM / 16];        // fp8 W*SW, [n][k]

// ---------------- helpers ---------------------------------------------------
__device__ __forceinline__ void red_add_v4(float4* addr, float4 v) {
    asm volatile("red.global.add.v4.f32 [%0], {%1,%2,%3,%4};"
                 :: "l"(addr), "f"(v.x), "f"(v.y), "f"(v.z), "f"(v.w)
                 : "memory");
}

__device__ __forceinline__ uint32_t smem_u32(const void* p) {
    uint32_t a;
    asm("{ .reg .u64 t; cvta.to.shared.u64 t, %1; cvt.u32.u64 %0, t; }" : "=r"(a) : "l"(p));
    return a;
}

__device__ __forceinline__ void cp16(void* dst_smem, const void* src) {
    asm volatile("cp.async.ca.shared.global [%0], [%1], 16;"
                 :: "r"(smem_u32(dst_smem)), "l"(src) : "memory");
}

__device__ __forceinline__ void ldsm_x4(uint32_t* r, uint32_t addr) {
    asm volatile("ldmatrix.sync.aligned.m8n8.x4.shared.b16 {%0,%1,%2,%3}, [%4];"
                 : "=r"(r[0]), "=r"(r[1]), "=r"(r[2]), "=r"(r[3]) : "r"(addr));
}

__device__ __forceinline__ void mma_fp8(float* c, const uint32_t* a,
                                        uint32_t b0, uint32_t b1) {
    asm volatile(
        "mma.sync.aligned.m16n8k32.row.col.f32.e4m3.e4m3.f32 "
        "{%0,%1,%2,%3}, {%4,%5,%6,%7}, {%8,%9}, {%0,%1,%2,%3};"
        : "+f"(c[0]), "+f"(c[1]), "+f"(c[2]), "+f"(c[3])
        : "r"(a[0]), "r"(a[1]), "r"(a[2]), "r"(a[3]), "r"(b0), "r"(b1));
}

__device__ __forceinline__ uint32_t f2h2(float a, float b) {
    __half2 h = __halves2half2(__float2half_rn(a), __float2half_rn(b));
    uint32_t u; memcpy(&u, &h, 4);
    return u;
}

// pack 4 floats -> 4 e4m3 bytes (byte0 = v0 ... byte3 = v3)
__device__ __forceinline__ uint32_t f2e4m3x4(float v0, float v1, float v2, float v3) {
    uint16_t lo, hi;
    asm("cvt.rn.satfinite.e4m3x2.f32 %0, %1, %2;" : "=h"(lo) : "f"(v1), "f"(v0));
    asm("cvt.rn.satfinite.e4m3x2.f32 %0, %1, %2;" : "=h"(hi) : "f"(v3), "f"(v2));
    return (uint32_t)lo | ((uint32_t)hi << 16);
}

// --- init -------------------------------------------------------------------
__global__ void init_kernel() {
    int i = blockIdx.x * blockDim.x + threadIdx.x;
    if (i < N_GRAPHS * HID / 4) g_pooled[i] = make_float4(0.f, 0.f, 0.f, 0.f);
    if (i < N_GRAPHS)           g_counts[i] = 0.f;
    if (i < N_NODES)            g_cnt[i] = 0;
}

__global__ void edge_bin_kernel(const int* __restrict__ ei) {
    int e = blockIdx.x * blockDim.x + threadIdx.x;
    if (e >= N_EDGES) return;
    int src = __ldg(&ei[e]);
    int dst = __ldg(&ei[N_EDGES + e]);
    int pos = atomicAdd(&g_cnt[dst], 1);
    if (pos < CSR_CAP) g_csr[dst * CSR_CAP + pos] = src;
}

__global__ void dinv_kernel() {
    int n = blockIdx.x * blockDim.x + threadIdx.x;
    if (n < N_NODES) g_dinv[n] = rsqrtf((float)(g_cnt[n] + 1));
}

// --- convert x -> fp8(x*dinv*SX), [m][k]; thread = 16 k values --------------
__global__ __launch_bounds__(256) void convert_x_kernel(const float4* __restrict__ X4) {
    constexpr int TOT = N_NODES * IN_DIM / 16;      // uint4 outputs
    int id = blockIdx.x * blockDim.x + threadIdx.x;
    if (id >= TOT) return;
    int row = id >> 5;                              // 32 threads per row
    float d = __ldg(&g_dinv[row]) * SX;
    float4 v[4];
    #pragma unroll
    for (int q = 0; q < 4; q++) v[q] = __ldg(&X4[id * 4 + q]);
    uint4 o;
    o.x = f2e4m3x4(v[0].x * d, v[0].y * d, v[0].z * d, v[0].w * d);
    o.y = f2e4m3x4(v[1].x * d, v[1].y * d, v[1].z * d, v[1].w * d);
    o.z = f2e4m3x4(v[2].x * d, v[2].y * d, v[2].z * d, v[2].w * d);
    o.w = f2e4m3x4(v[3].x * d, v[3].y * d, v[3].z * d, v[3].w * d);
    g_x8[id] = o;
}

// --- convert W [k][n] fp32 -> [n][k] fp8*SW (smem-tiled transpose) ----------
// grid (HID/32, IN_DIM/32), block (32,8)
__global__ void convert_w_kernel(const float* __restrict__ W) {
    __shared__ float t[32][33];
    int n0 = blockIdx.x * 32;
    int k0 = blockIdx.y * 32;
    int tx = threadIdx.x, ty = threadIdx.y;
    #pragma unroll
    for (int r = 0; r < 4; r++)
        t[ty + 8 * r][tx] = W[(size_t)(k0 + ty + 8 * r) * HID + n0 + tx];
    __syncthreads();
    int tid  = ty * 32 + tx;
    int orow = tid >> 3;        // 0..31 (n within tile)
    int kq   = tid & 7;         // 4-byte k group
    uint32_t o = f2e4m3x4(t[kq * 4 + 0][orow] * SW, t[kq * 4 + 1][orow] * SW,
                          t[kq * 4 + 2][orow] * SW, t[kq * 4 + 3][orow] * SW);
    uint32_t* out = (uint32_t*)g_w8;
    out[((size_t)(n0 + orow) * IN_DIM + k0) / 4 + kq] = o;
}

// --- fp8 tensor-core GEMM: hs = fp16( (x*dinv) @ W ) ------------------------
// 256 threads, 8 warps (4m x 2n), warp tile 32x64, 2-stage cp.async, ldmatrix.
__global__ __launch_bounds__(256, 2) void gemm_mma_kernel() {
    extern __shared__ char sm[];
    const uint32_t smaddr = smem_u32(sm);

    const int tid  = threadIdx.x;
    const int lane = tid & 31;
    const int wid  = tid >> 5;
    const int warp_m = wid & 3;
    const int warp_n = wid >> 2;
    const int quad  = lane >> 2;
    const int tig   = lane & 3;

    const int m0 = blockIdx.y * TILE_M;
    const int n0 = blockIdx.x * TILE_N;

    const char* x8 = (const char*)g_x8;
    const char* w8 = (const char*)g_w8;

    float acc[2][8][4];
    #pragma unroll
    for (int i = 0; i < 2; i++)
        #pragma unroll
        for (int j = 0; j < 8; j++)
            #pragma unroll
            for (int c = 0; c < 4; c++) acc[i][j][c] = 0.f;

    // ldmatrix lane address components (BYTES)
    const int a_base = (warp_m * 32 + (lane & 15)) * RSTRB + ((lane & 16) ? 16 : 0);
    const int b_row  = ((lane >> 4) & 1) * 8 + (lane & 7);
    const int b_base = OFF_B + (warp_n * 64 + b_row) * RSTRB + ((lane & 8) ? 16 : 0);

    auto load_stage = [&](int s, int chunk) {
        const int k0 = chunk * TKB;
        char* st = sm + s * STAGEB;
        #pragma unroll
        for (int r = 0; r < 2; r++) {
            int idx = tid + 256 * r;
            int row = idx >> 2;          // 0..127
            int c   = idx & 3;           // 4 x 16B
            int gr  = m0 + row; if (gr >= N_NODES) gr = 0;
            cp16(st + row * RSTRB + c * 16,
                 x8 + (size_t)gr * IN_DIM + k0 + c * 16);
        }
        #pragma unroll
        for (int r = 0; r < 2; r++) {
            int idx = tid + 256 * r;
            int row = idx >> 2;
            int c   = idx & 3;
            cp16(st + OFF_B + row * RSTRB + c * 16,
                 w8 + (size_t)(n0 + row) * IN_DIM + k0 + c * 16);
        }
    };

    load_stage(0, 0);
    asm volatile("cp.async.commit_group;" ::: "memory");

    for (int chunk = 0; chunk < NCHUNK; chunk++) {
        if (chunk + 1 < NCHUNK) load_stage((chunk + 1) & 1, chunk + 1);
        asm volatile("cp.async.commit_group;" ::: "memory");
        asm volatile("cp.async.wait_group 1;" ::: "memory");
        __syncthreads();

        const uint32_t stg = smaddr + (uint32_t)(chunk & 1) * STAGEB;

        #pragma unroll
        for (int ks = 0; ks < 2; ks++) {
            const int kb = ks * 32;      // 32 fp8 bytes per k-step
            uint32_t a0[4], a1[4];
            uint32_t aa = stg + (uint32_t)(a_base + kb);
            ldsm_x4(a0, aa);
            ldsm_x4(a1, aa + 16 * RSTRB);
            #pragma unroll
            for (int p = 0; p < 4; p++) {
                uint32_t bh[4];
                ldsm_x4(bh, stg + (uint32_t)(b_base + p * 16 * RSTRB + kb));
                mma_fp8(acc[0][2 * p],     a0, bh[0], bh[1]);
                mma_fp8(acc[1][2 * p],     a1, bh[0], bh[1]);
                mma_fp8(acc[0][2 * p + 1], a0, bh[2], bh[3]);
                mma_fp8(acc[1][2 * p + 1], a1, bh[2], bh[3]);
            }
        }
        __syncthreads();
    }

    // ---- epilogue: unscale, store hs as fp16 ------------------------------
    __half* hsh = (__half*)g_hsh;
    #pragma unroll
    for (int i = 0; i < 2; i++) {
        const int r0 = m0 + warp_m * 32 + i * 16 + quad;
        const int r1 = r0 + 8;
        const bool v0 = r0 < N_NODES;
        const bool v1 = r1 < N_NODES;
        #pragma unroll
        for (int j = 0; j < 8; j++) {
            const int col = n0 + warp_n * 64 + j * 8 + tig * 2;
            if (v0)
                *(uint32_t*)(hsh + (size_t)r0 * HID + col) =
                    f2h2(acc[i][j][0] * RSCALE, acc[i][j][1] * RSCALE);
            if (v1)
                *(uint32_t*)(hsh + (size_t)r1 * HID + col) =
                    f2h2(acc[i][j][2] * RSCALE, acc[i][j][3] * RSCALE);
        }
    }
}

// --- gather + relu + pool: one node per 64 threads, fp16 rows ---------------
__global__ __launch_bounds__(256) void gather_pool_kernel(
    const int* __restrict__ batch, const float* __restrict__ b)
{
    int t = blockIdx.x * blockDim.x + threadIdx.x;
    int n = t >> 6;
    int lane = t & 63;
    if (n >= N_NODES) return;

    int cnt = g_cnt[n];
    if (cnt > CSR_CAP) cnt = CSR_CAP;
    const int* lst = g_csr + n * CSR_CAP;

    auto addrow = [&](float4& a, uint2 raw) {
        __half2 p0, p1;
        memcpy(&p0, &raw.x, 4);
        memcpy(&p1, &raw.y, 4);
        float2 f0 = __half22float2(p0);
        float2 f1 = __half22float2(p1);
        a.x += f0.x; a.y += f0.y; a.z += f1.x; a.w += f1.y;
    };

    float4 a = make_float4(0.f, 0.f, 0.f, 0.f);
    addrow(a, __ldg(&g_hsh[(size_t)n * 64 + lane]));   // self loop

    int i = 0;
    for (; i + 8 <= cnt; i += 8) {
        int s[8];
        #pragma unroll
        for (int q = 0; q < 8; q++) s[q] = __ldg(&lst[i + q]);
        uint2 v[8];
        #pragma unroll
        for (int q = 0; q < 8; q++) v[q] = __ldg(&g_hsh[(size_t)s[q] * 64 + lane]);
        #pragma unroll
        for (int q = 0; q < 8; q++) addrow(a, v[q]);
    }
    for (; i < cnt; i++) {
        int s = __ldg(&lst[i]);
        addrow(a, __ldg(&g_hsh[(size_t)s * 64 + lane]));
    }

    float d = g_dinv[n];
    float4 bb = __ldg((const float4*)b + lane);
    float4 v;
    v.x = fmaxf(fmaf(a.x, d, bb.x), 0.f);
    v.y = fmaxf(fmaf(a.y, d, bb.y), 0.f);
    v.z = fmaxf(fmaf(a.z, d, bb.z), 0.f);
    v.w = fmaxf(fmaf(a.w, d, bb.w), 0.f);

    int g = __ldg(&batch[n]);
    red_add_v4(&g_pooled[(size_t)g * 64 + lane], v);
    if (lane == 0) atomicAdd(&g_counts[g], 1.f);
}

// --- head --------------------------------------------------------------------
__global__ void head_kernel(
    const float* __restrict__ lin_w, const float* __restrict__ lin_b,
    float* __restrict__ out)
{
    __shared__ float red[256];
    int g = blockIdx.x;
    int t = threadIdx.x;
    const float* pooled = (const float*)g_pooled;
    red[t] = pooled[g * HID + t] * __ldg(&lin_w[t]);
    __syncthreads();
    #pragma unroll
    for (int s = 128; s > 0; s >>= 1) {
        if (t < s) red[t] += red[t + s];
        __syncthreads();
    }
    if (t == 0) {
        float cnt = fmaxf(g_counts[g], 1.f);
        float z = red[0] / cnt + __ldg(&lin_b[0]);
        out[g] = 1.f / (1.f + expf(-z));
    }
}

// ---------------------------------------------------------------------------
extern "C" void kernel_launch(void* const* d_in, const int* in_sizes, int n_in,
                              void* d_out, int out_size) {
    const float* x     = (const float*)d_in[0];
    const int*   ei    = (const int*)d_in[1];
    const int*   batch = (const int*)d_in[2];
    const float* W     = (const float*)d_in[3];
    const float* b     = (const float*)d_in[4];
    const float* lin_w = (const float*)d_in[5];
    const float* lin_b = (const float*)d_in[6];
    float*       out   = (float*)d_out;

    static bool attr_set = false;
    if (!attr_set) {
        cudaFuncSetAttribute(gemm_mma_kernel,
                             cudaFuncAttributeMaxDynamicSharedMemorySize, SMEM_BYTES);
        attr_set = true;
    }

    init_kernel<<<(N_GRAPHS * HID + 255) / 256, 256>>>();
    edge_bin_kernel<<<(N_EDGES + 255) / 256, 256>>>(ei);
    dinv_kernel<<<(N_NODES + 255) / 256, 256>>>();
    convert_x_kernel<<<(N_NODES * IN_DIM / 16 + 255) / 256, 256>>>((const float4*)x);
    convert_w_kernel<<<dim3(HID / 32, IN_DIM / 32), dim3(32, 8)>>>(W);
    gemm_mma_kernel<<<dim3(HID / TILE_N, (N_NODES + TILE_M - 1) / TILE_M),
                      256, SMEM_BYTES>>>();
    gather_pool_kernel<<<(N_NODES * 64 + 255) / 256, 256>>>(batch, b);
    head_kernel<<<N_GRAPHS, 256>>>(lin_w, lin_b, out);
}